// round 16
// baseline (speedup 1.0000x reference)
#include <cuda_runtime.h>
#include <cuda_fp16.h>
#include <cstdint>
#include <math.h>

// dims
#define N_  16
#define C_  32
#define V_  2048
#define VC_ 256
#define S_  64
#define L_  12
#define CO_ 32
#define NL_ 192
#define M_  6144

#define N1F 0.8f
#define N2F 0.2f
#define N3F 0.2f
#define N4F 0.2f

#define HFSZ (N_ * CO_ * V_ * L_)
#define HCSZ (N_ * CO_ * VC_ * L_)

// ---------------- scratch ----------------
__device__ float  g_X    [V_  * M_];
__device__ __half g_X16  [V_  * M_];
__device__ __half g_Z23h [2 * V_  * M_];
__device__ float  g_HF   [V_  * M_];
__device__ __half g_HF16 [V_  * M_];
__device__ float  g_Xc   [VC_ * M_];
__device__ __half g_Xc16 [VC_ * M_];
__device__ __half g_Zc23h[2 * VC_ * M_];
__device__ float  g_HC   [VC_ * M_];
__device__ __half g_HC16 [VC_ * M_];
__device__ float  g_Sxg  [S_  * M_];
__device__ float  g_SxgP [S_  * M_];
__device__ __half g_Zs23h[2 * S_  * M_];
__device__ float  g_HS   [S_  * M_];
__device__ __half g_HS16 [S_  * M_];
__device__ float  g_part [2 * VC_ * M_];
__device__ float  g_asmat[S_ * S_];
__device__ __half g_sup01h[2 * S_ * S_];
__device__ __half g_acsT16[S_ * VC_];
__device__ __half g_afcT16[VC_ * V_];
__device__ __half g_afc16 [V_ * VC_];
__device__ __half g_acs16 [VC_ * S_];
__device__ __half g_sup16 [2 * V_ * V_];
__device__ __half g_supc16[2 * VC_ * VC_];

__device__ __forceinline__ unsigned pack_h2(float lo, float hi) {
    unsigned r;
    asm("cvt.rn.f16x2.f32 %0, %1, %2;" : "=r"(r) : "f"(hi), "f"(lo));
    return r;
}
__device__ __forceinline__ uint32_t smem_u32(const void* p) {
    uint32_t a;
    asm("{ .reg .u64 t; cvta.to.shared.u64 t, %1; cvt.u32.u64 %0, t; }" : "=r"(a) : "l"(p));
    return a;
}
#define LDSM4T(r0, r1, r2, r3, addr) \
    asm volatile("ldmatrix.sync.aligned.m8n8.x4.trans.shared.b16 {%0,%1,%2,%3}, [%4];" \
                 : "=r"(r0), "=r"(r1), "=r"(r2), "=r"(r3) : "r"(addr))

__device__ __forceinline__ int out_coff(int m, int nodes) {
    int o = m / NL_;
    int rem = m - o * NL_;
    int nn = rem / L_;
    int l = rem - nn * L_;
    return ((nn * CO_ + o) * nodes) * L_ + l;
}

// ---------------- transposes / converts ----------------
__global__ void transpose_in(const float* __restrict__ x) {
    int idx = blockIdx.x * blockDim.x + threadIdx.x;
    if (idx >= N_ * C_ * V_ * L_) return;
    int l = idx % L_;
    int v = (idx / L_) % V_;
    int c = (idx / (L_ * V_)) % C_;
    int n = idx / (L_ * V_ * C_);
    float val = x[idx];
    size_t o = (size_t)v * M_ + c * NL_ + n * L_ + l;
    g_X[o]   = val;
    g_X16[o] = __float2half_rn(val);
}

__global__ void transpose_acs(const float* __restrict__ acs) {
    int idx = blockIdx.x * blockDim.x + threadIdx.x;
    if (idx >= S_ * VC_) return;
    int s = idx / VC_, w = idx % VC_;
    g_acsT16[idx] = __float2half_rn(acs[w * S_ + s]);
}

__global__ void transpose_afc(const float* __restrict__ afc) {
    int idx = blockIdx.x * blockDim.x + threadIdx.x;
    if (idx >= VC_ * V_) return;
    int w = idx / V_, v = idx % V_;
    g_afcT16[idx] = __float2half_rn(afc[(size_t)v * VC_ + w]);
}

__global__ void cvt_to_h(const float* __restrict__ src, __half* __restrict__ dst, int n4) {
    int i = blockIdx.x * blockDim.x + threadIdx.x;
    if (i >= n4) return;
    float4 v = reinterpret_cast<const float4*>(src)[i];
    reinterpret_cast<uint2*>(dst)[i] = make_uint2(pack_h2(v.x, v.y), pack_h2(v.z, v.w));
}

// ---------------- channel mix: H fp32, Z2/Z3 fp16 ----------------
__global__ void chanmix(const float* __restrict__ Xin,
                        const float* __restrict__ W,
                        const float* __restrict__ b,
                        float* __restrict__ H,
                        __half* __restrict__ Z2,
                        __half* __restrict__ Z3) {
    __shared__ float4 sW[32 * 24];
    __shared__ float  sb[32];
    int r = blockIdx.x;
    const float* xr = Xin + (size_t)r * M_;
    for (int i = threadIdx.x; i < 32 * 24; i += 192)
        sW[i] = reinterpret_cast<const float4*>(W)[i];
    if (threadIdx.x < 32) sb[threadIdx.x] = b[threadIdx.x];
    __syncthreads();

    int nl = threadIdx.x;
    float xv[32];
    #pragma unroll
    for (int c = 0; c < 32; c++) xv[c] = xr[c * NL_ + nl];

    for (int o = 0; o < 32; o++) {
        const float4* wr = &sW[o * 24];
        float a0 = sb[o], a1 = 0.f, a2 = 0.f;
        #pragma unroll
        for (int c4 = 0; c4 < 8; c4++) {
            float4 w0 = wr[c4];
            float4 w1 = wr[8 + c4];
            float4 w2 = wr[16 + c4];
            float x0 = xv[c4 * 4], x1 = xv[c4 * 4 + 1], x2 = xv[c4 * 4 + 2], x3 = xv[c4 * 4 + 3];
            a0 = fmaf(w0.x, x0, fmaf(w0.y, x1, fmaf(w0.z, x2, fmaf(w0.w, x3, a0))));
            a1 = fmaf(w1.x, x0, fmaf(w1.y, x1, fmaf(w1.z, x2, fmaf(w1.w, x3, a1))));
            a2 = fmaf(w2.x, x0, fmaf(w2.y, x1, fmaf(w2.z, x2, fmaf(w2.w, x3, a2))));
        }
        size_t base = (size_t)r * M_ + o * NL_ + nl;
        H[base]  = a0;
        Z2[base] = __float2half_rn(a1);
        Z3[base] = __float2half_rn(a2);
    }
}

// ---------------- TN GEMM (fp16 operands only) ----------------
// C[mo,mn] (op) sum_k A[k,mo]*B[k,mn];  mode 0: =, 1: +=, 2: += alpha*relu
// c16: optional fp16 duplicate of C. outp: optional transposed output write.
#define STAGE_B 8192
__global__ void __launch_bounds__(256, 2)
gemm_fp16(const __half* __restrict__ A, const __half* __restrict__ B, float* __restrict__ C,
          int Mo, int Mn, int kslice, int mode, float alpha,
          __half* __restrict__ c16,
          float* __restrict__ outp, int nodes, int obase) {
    __shared__ __align__(16) char smh[3 * STAGE_B];
    const uint32_t sbase = smem_u32(smh);

    const int zz = blockIdx.z;
    A += (size_t)zz * kslice * Mo;
    B += (size_t)zz * kslice * Mn;
    C += (size_t)zz * Mo * Mn * (gridDim.z > 1 ? 1 : 0);

    const int bm = blockIdx.y * 128;
    const int bn = blockIdx.x * 128;
    const int tid  = threadIdx.x;
    const int lane = tid & 31;
    const int warp = tid >> 5;
    const int m_base = (warp >> 2) * 64;
    const int n_base = (warp & 3) * 32;

    const int lrow0 = warp;
    const int lc4   = (tid & 31) << 2;
    const int mg    = lc4 >> 3;
    const int hoff  = (lc4 & 7) * 2;

    const int gA  = lane >> 3;
    const int krA = (lane & 7) | ((gA & 2) << 2);
    int offA[4];
    #pragma unroll
    for (int i = 0; i < 4; i++) {
        int mgA = ((m_base + i * 16) >> 3) + (gA & 1);
        offA[i] = krA * 256 + ((mgA ^ (krA & 7)) << 4);
    }
    const int gB  = lane >> 3;
    const int krB = (lane & 7) | ((gB & 1) << 3);
    int offB[2];
    #pragma unroll
    for (int jp = 0; jp < 2; jp++) {
        int ngB = ((n_base + jp * 16) >> 3) + (gB >> 1);
        offB[jp] = krB * 256 + ((ngB ^ (krB & 7)) << 4);
    }

    float acc[4][4][4];
    #pragma unroll
    for (int i = 0; i < 4; i++)
        #pragma unroll
        for (int j = 0; j < 4; j++)
            #pragma unroll
            for (int t = 0; t < 4; t++) acc[i][j][t] = 0.f;

    const int nch = kslice >> 4;
    uint2 ha[2], hb[2];

    auto load_regs = [&](int ch) {
        if (ch >= nch) return;
        const int k0 = ch << 4;
        const bool aok = (bm + lc4 < Mo);
        #pragma unroll
        for (int h = 0; h < 2; h++) {
            const int kr = k0 + lrow0 + h * 8;
            ha[h] = aok ? *reinterpret_cast<const uint2*>(A + (size_t)kr * Mo + bm + lc4)
                        : make_uint2(0u, 0u);
            hb[h] = *reinterpret_cast<const uint2*>(B + (size_t)kr * Mn + bn + lc4);
        }
    };
    auto sts_regs = [&](int ch) {
        if (ch >= nch) return;
        char* stg = smh + (ch % 3) * STAGE_B;
        #pragma unroll
        for (int h = 0; h < 2; h++) {
            const int kr = lrow0 + h * 8;
            const int gsw = (mg ^ (kr & 7)) << 4;
            *reinterpret_cast<uint2*>(stg + kr * 256 + gsw + hoff) = ha[h];
            *reinterpret_cast<uint2*>(stg + 4096 + kr * 256 + gsw + hoff) = hb[h];
        }
    };

    load_regs(0);
    sts_regs(0);
    load_regs(1);

    for (int ch = 0; ch < nch; ch++) {
        sts_regs(ch + 1);
        load_regs(ch + 2);
        __syncthreads();

        const uint32_t a_s = sbase + (uint32_t)((ch % 3) * STAGE_B);
        const uint32_t b_s = a_s + 4096u;

        unsigned af[4][4];
        #pragma unroll
        for (int i = 0; i < 4; i++)
            LDSM4T(af[i][0], af[i][1], af[i][2], af[i][3], a_s + offA[i]);
        unsigned bf[4][2];
        #pragma unroll
        for (int jp = 0; jp < 2; jp++) {
            unsigned r0, r1, r2, r3;
            LDSM4T(r0, r1, r2, r3, b_s + offB[jp]);
            bf[jp * 2][0] = r0;  bf[jp * 2][1] = r1;
            bf[jp * 2 + 1][0] = r2;  bf[jp * 2 + 1][1] = r3;
        }

        #pragma unroll
        for (int i = 0; i < 4; i++)
            #pragma unroll
            for (int j = 0; j < 4; j++) {
                asm volatile(
                    "mma.sync.aligned.m16n8k16.row.col.f32.f16.f16.f32 "
                    "{%0,%1,%2,%3},{%4,%5,%6,%7},{%8,%9},{%0,%1,%2,%3};\n"
                    : "+f"(acc[i][j][0]), "+f"(acc[i][j][1]),
                      "+f"(acc[i][j][2]), "+f"(acc[i][j][3])
                    : "r"(af[i][0]), "r"(af[i][1]), "r"(af[i][2]), "r"(af[i][3]),
                      "r"(bf[j][0]), "r"(bf[j][1]));
            }
    }

    const int gid = lane >> 2;
    const int qc  = lane & 3;

    int coff[4][2];
    if (outp) {
        #pragma unroll
        for (int j = 0; j < 4; j++) {
            int c0 = bn + n_base + j * 8 + qc * 2;
            coff[j][0] = out_coff(c0, nodes);
            coff[j][1] = out_coff(c0 + 1, nodes);
        }
    }

    #pragma unroll
    for (int i = 0; i < 4; i++) {
        int r0 = bm + m_base + i * 16 + gid;
        int r1 = r0 + 8;
        #pragma unroll
        for (int j = 0; j < 4; j++) {
            int col = bn + n_base + j * 8 + qc * 2;
            #pragma unroll
            for (int h = 0; h < 2; h++) {
                int row = h ? r1 : r0;
                if (row >= Mo) continue;
                float x0 = acc[i][j][h * 2 + 0];
                float x1 = acc[i][j][h * 2 + 1];
                size_t cidx = (size_t)row * Mn + col;
                float2 r;
                if (mode == 0) {
                    r = make_float2(x0, x1);
                } else {
                    float2 p = *reinterpret_cast<const float2*>(C + cidx);
                    if (mode == 1) {
                        r = make_float2(p.x + x0, p.y + x1);
                    } else {
                        r = make_float2(p.x + alpha * fmaxf(x0, 0.f),
                                        p.y + alpha * fmaxf(x1, 0.f));
                    }
                }
                *reinterpret_cast<float2*>(C + cidx) = r;
                if (c16)
                    *reinterpret_cast<unsigned*>(reinterpret_cast<char*>(c16) + cidx * 2) =
                        pack_h2(r.x, r.y);
                if (outp) {
                    outp[obase + coff[j][0] + row * L_] = r.x;
                    outp[obase + coff[j][1] + row * L_] = r.y;
                }
            }
        }
    }
}

// ---------------- split-K reduce (optional fp16 dup + transposed out) ----------------
__global__ void reduceN(const float* __restrict__ p, float* __restrict__ C,
                        int n, int R, int mode, float alpha,
                        __half* __restrict__ c16,
                        float* __restrict__ outp, int nodes, int obase) {
    int idx = blockIdx.x * blockDim.x + threadIdx.x;
    if (idx >= n) return;
    float s = 0.f;
    for (int r = 0; r < R; r++) s += p[(size_t)r * n + idx];
    float v;
    if (mode == 0)      v = s;
    else if (mode == 1) v = C[idx] + s;
    else                v = C[idx] + alpha * fmaxf(s, 0.f);
    C[idx] = v;
    if (c16) c16[idx] = __float2half_rn(v);
    if (outp) {
        int row = idx / M_, col = idx % M_;
        outp[obase + out_coff(col, nodes) + row * L_] = v;
    }
}

// ---------------- permute + as_mat + sup ----------------
__global__ void permute_sxg() {
    int idx = blockIdx.x * blockDim.x + threadIdx.x;
    if (idx >= S_ * M_) return;
    int t = idx / M_, j = idx % M_;
    int cp = j & 31, np = (j >> 5) & 15, lp = j >> 9;
    g_SxgP[idx] = g_Sxg[(size_t)t * M_ + cp * NL_ + np * L_ + lp];
}

__global__ void asmat_kernel() {
    __shared__ float Ps[M_];
    int s = blockIdx.x;
    for (int i = threadIdx.x; i < M_; i += blockDim.x)
        Ps[i] = g_Sxg[(size_t)s * M_ + i];
    __syncthreads();
    int warp = threadIdx.x >> 5, lane = threadIdx.x & 31;
    for (int t = warp; t < S_; t += 8) {
        float acc = 0.f;
        const float* qt = &g_SxgP[(size_t)t * M_];
        for (int j = lane; j < M_; j += 32)
            acc = fmaf(Ps[j], qt[j], acc);
        #pragma unroll
        for (int o = 16; o > 0; o >>= 1) acc += __shfl_down_sync(0xffffffffu, acc, o);
        if (lane == 0) {
            float v = acc - 0.5f;
            g_asmat[s * S_ + t] = v > 0.f ? v : 0.f;
        }
    }
}

__global__ void supmat_kernel() {
    __shared__ float Ms[S_ * S_];
    int t = threadIdx.x;
    for (int i = t; i < S_ * S_; i += blockDim.x) Ms[i] = g_asmat[i];
    __syncthreads();
    if (t >= S_) return;
    float vals[S_];
    {
        float rs = 0.f;
        for (int u = 0; u < S_; u++) rs += Ms[t * S_ + u];
        float dinv = rs > 0.f ? 1.f / rs : 0.f;
        float mx = -1e30f;
        for (int u = 0; u < S_; u++) { vals[u] = Ms[t * S_ + u] * dinv; mx = fmaxf(mx, vals[u]); }
        float se = 0.f;
        for (int u = 0; u < S_; u++) { vals[u] = expf(vals[u] - mx); se += vals[u]; }
        float inv = 1.f / se;
        for (int u = 0; u < S_; u++) g_sup01h[t * S_ + u] = __float2half_rn(vals[u] * inv);
    }
    {
        float cs = 0.f;
        for (int u = 0; u < S_; u++) cs += Ms[u * S_ + t];
        float dinv = cs > 0.f ? 1.f / cs : 0.f;
        float mx = -1e30f;
        for (int u = 0; u < S_; u++) { vals[u] = Ms[u * S_ + t] * dinv; mx = fmaxf(mx, vals[u]); }
        float se = 0.f;
        for (int u = 0; u < S_; u++) { vals[u] = expf(vals[u] - mx); se += vals[u]; }
        float inv = 1.f / se;
        for (int u = 0; u < S_; u++) g_sup01h[S_ * S_ + t * S_ + u] = __float2half_rn(vals[u] * inv);
    }
}

// ---------------- host side ----------------
static inline void launch_gemm(const void* A, const void* B, void* C,
                               int Mo, int K, int mode, float alpha,
                               void* c16 = nullptr,
                               void* outp = nullptr, int nodes = 0, int obase = 0) {
    dim3 grid(M_ / 128, (Mo + 127) / 128, 1);
    gemm_fp16<<<grid, 256>>>((const __half*)A, (const __half*)B, (float*)C,
                             Mo, M_, K, mode, alpha, (__half*)c16,
                             (float*)outp, nodes, obase);
}
static inline void launch_gemm_sk(const void* A, const void* B, void* part, void* C,
                                  int Mo, int K, int R, int mode, float alpha,
                                  void* c16 = nullptr,
                                  void* outp = nullptr, int nodes = 0, int obase = 0) {
    dim3 grid(M_ / 128, (Mo + 127) / 128, R);
    gemm_fp16<<<grid, 256>>>((const __half*)A, (const __half*)B, (float*)part,
                             Mo, M_, K / R, 0, 0.f, nullptr, nullptr, 0, 0);
    int n = Mo * M_;
    reduceN<<<(n + 255) / 256, 256>>>((const float*)part, (float*)C, n, R, mode, alpha,
                                      (__half*)c16, (float*)outp, nodes, obase);
}

extern "C" void kernel_launch(void* const* d_in, const int* in_sizes, int n_in,
                              void* d_out, int out_size) {
    (void)in_sizes; (void)n_in; (void)out_size;
    const float* x         = (const float*)d_in[0];
    const float* support   = (const float*)d_in[1];
    const float* support_c = (const float*)d_in[2];
    const float* acs       = (const float*)d_in[3];
    const float* afc       = (const float*)d_in[4];
    const float* W         = (const float*)d_in[5];
    const float* b         = (const float*)d_in[6];
    float* out = (float*)d_out;

    void *pX, *pX16, *pZ23h, *pHF, *pHF16, *pXc, *pXc16, *pZc23h, *pHC, *pHC16;
    void *pSxg, *pZs23h, *pHS, *pHS16, *psup01h, *pacsT16, *pafcT16;
    void *pafc16, *pacs16, *ppart, *psup16, *psupc16;
    cudaGetSymbolAddress(&pX, g_X);           cudaGetSymbolAddress(&pX16, g_X16);
    cudaGetSymbolAddress(&pZ23h, g_Z23h);     cudaGetSymbolAddress(&pHF, g_HF);
    cudaGetSymbolAddress(&pHF16, g_HF16);     cudaGetSymbolAddress(&pXc, g_Xc);
    cudaGetSymbolAddress(&pXc16, g_Xc16);     cudaGetSymbolAddress(&pZc23h, g_Zc23h);
    cudaGetSymbolAddress(&pHC, g_HC);         cudaGetSymbolAddress(&pHC16, g_HC16);
    cudaGetSymbolAddress(&pSxg, g_Sxg);       cudaGetSymbolAddress(&pZs23h, g_Zs23h);
    cudaGetSymbolAddress(&pHS, g_HS);         cudaGetSymbolAddress(&pHS16, g_HS16);
    cudaGetSymbolAddress(&psup01h, g_sup01h); cudaGetSymbolAddress(&pacsT16, g_acsT16);
    cudaGetSymbolAddress(&pafcT16, g_afcT16); cudaGetSymbolAddress(&pafc16, g_afc16);
    cudaGetSymbolAddress(&pacs16, g_acs16);   cudaGetSymbolAddress(&ppart, g_part);
    cudaGetSymbolAddress(&psup16, g_sup16);   cudaGetSymbolAddress(&psupc16, g_supc16);

    __half* Z2  = (__half*)pZ23h;
    __half* Z3  = Z2 + (size_t)V_ * M_;
    __half* Zc2 = (__half*)pZc23h;
    __half* Zc3 = Zc2 + (size_t)VC_ * M_;
    __half* Zs2 = (__half*)pZs23h;
    __half* Zs3 = Zs2 + (size_t)S_ * M_;

    // 1. layout prep (fp16 world)
    transpose_in<<<(N_ * C_ * V_ * L_ + 255) / 256, 256>>>(x);
    transpose_acs<<<(S_ * VC_ + 255) / 256, 256>>>(acs);
    transpose_afc<<<(VC_ * V_ + 255) / 256, 256>>>(afc);
    cvt_to_h<<<(2 * V_ * V_ / 4 + 255) / 256, 256>>>(support, (__half*)psup16, 2 * V_ * V_ / 4);
    cvt_to_h<<<(2 * VC_ * VC_ / 4 + 255) / 256, 256>>>(support_c, (__half*)psupc16, 2 * VC_ * VC_ / 4);
    cvt_to_h<<<(V_ * VC_ / 4 + 255) / 256, 256>>>(afc, (__half*)pafc16, V_ * VC_ / 4);
    cvt_to_h<<<(VC_ * S_ / 4 + 255) / 256, 256>>>(acs, (__half*)pacs16, VC_ * S_ / 4);

    // 2. fine level
    chanmix<<<V_, 192>>>((const float*)pX, W, b, (float*)pHF, Z2, Z3);
    launch_gemm(psup16, pZ23h, pHF, V_, 2 * V_, 1, 1.f);

    // 3. coarse level
    launch_gemm_sk(pafc16, pX16, ppart, pXc, VC_, V_, 2, 0, 0.f, pXc16);
    chanmix<<<VC_, 192>>>((const float*)pXc, W, b, (float*)pHC, Zc2, Zc3);
    launch_gemm_sk(psupc16, pZc23h, ppart, pHC, VC_, 2 * VC_, 2, 1, 0.f);

    // 4. super level input
    launch_gemm_sk(pacs16, pXc16, ppart, pSxg, S_, VC_, 4, 0, 0.f);

    // 5. data-dependent super supports (exact fp32)
    permute_sxg<<<(S_ * M_ + 255) / 256, 256>>>();
    asmat_kernel<<<S_, 256>>>();
    supmat_kernel<<<1, 64>>>();

    // 6. super gcn
    chanmix<<<S_, 192>>>((const float*)pSxg, W, b, (float*)pHS, Zs2, Zs3);
    launch_gemm_sk(psup01h, pZs23h, ppart, pHS, S_, 2 * S_, 2, 1, 0.f, pHS16);

    // 7. fusions; fp16 dups feed the next stage; final writers emit outputs
    launch_gemm_sk(pacsT16, pHS16, ppart, pHC, VC_, S_, 2, 2, N1F, pHC16);
    launch_gemm(pafcT16, pHC16, pHF, V_, VC_, 2, N2F, pHF16, out, V_, 0);
    launch_gemm_sk(pafc16, pHF16, ppart, pHC, VC_, V_, 2, 2, N3F, pHC16, out, VC_, HFSZ);
    launch_gemm_sk(pacs16, pHC16, ppart, pHS, S_, VC_, 4, 2, N4F, nullptr, out, S_, HFSZ + HCSZ);
}

// round 17
// speedup vs baseline: 1.0233x; 1.0233x over previous
#include <cuda_runtime.h>
#include <cuda_fp16.h>
#include <cstdint>
#include <math.h>

// dims
#define N_  16
#define C_  32
#define V_  2048
#define VC_ 256
#define S_  64
#define L_  12
#define CO_ 32
#define NL_ 192
#define M_  6144

#define N1F 0.8f
#define N2F 0.2f
#define N3F 0.2f
#define N4F 0.2f

#define HFSZ (N_ * CO_ * V_ * L_)
#define HCSZ (N_ * CO_ * VC_ * L_)

// ---------------- scratch ----------------
__device__ float  g_X    [V_  * M_];
__device__ __half g_Z23h [2 * V_  * M_];
__device__ float  g_HF   [V_  * M_];
__device__ float  g_Xc   [VC_ * M_];
__device__ __half g_Zc23h[2 * VC_ * M_];
__device__ float  g_HC   [VC_ * M_];
__device__ float  g_Sxg  [S_  * M_];
__device__ float  g_SxgP [S_  * M_];
__device__ __half g_Zs23h[2 * S_  * M_];
__device__ float  g_HS   [S_  * M_];
__device__ float  g_part [2 * VC_ * M_];
__device__ float  g_asmatP[2 * S_ * S_];   // two j-half partials
__device__ __half g_sup01h[2 * S_ * S_];
__device__ float  g_acsT [S_ * VC_];
__device__ float  g_afcT [VC_ * V_];
__device__ __half g_sup16 [2 * V_ * V_];
__device__ __half g_supc16[2 * VC_ * VC_];

__device__ __forceinline__ unsigned pack_h2(float lo, float hi) {
    unsigned r;
    asm("cvt.rn.f16x2.f32 %0, %1, %2;" : "=r"(r) : "f"(hi), "f"(lo));
    return r;
}
__device__ __forceinline__ uint32_t smem_u32(const void* p) {
    uint32_t a;
    asm("{ .reg .u64 t; cvta.to.shared.u64 t, %1; cvt.u32.u64 %0, t; }" : "=r"(a) : "l"(p));
    return a;
}
#define LDSM4T(r0, r1, r2, r3, addr) \
    asm volatile("ldmatrix.sync.aligned.m8n8.x4.trans.shared.b16 {%0,%1,%2,%3}, [%4];" \
                 : "=r"(r0), "=r"(r1), "=r"(r2), "=r"(r3) : "r"(addr))

__device__ __forceinline__ int out_coff(int m, int nodes) {
    int o = m / NL_;
    int rem = m - o * NL_;
    int nn = rem / L_;
    int l = rem - nn * L_;
    return ((nn * CO_ + o) * nodes) * L_ + l;
}

// ---------------- transposes / converts ----------------
__global__ void transpose_in(const float* __restrict__ x) {
    int idx = blockIdx.x * blockDim.x + threadIdx.x;
    if (idx >= N_ * C_ * V_ * L_) return;
    int l = idx % L_;
    int v = (idx / L_) % V_;
    int c = (idx / (L_ * V_)) % C_;
    int n = idx / (L_ * V_ * C_);
    g_X[(size_t)v * M_ + c * NL_ + n * L_ + l] = x[idx];
}

// merged small transposes: acsT (fp32) + afcT (fp32)
__global__ void prep_t(const float* __restrict__ acs, const float* __restrict__ afc) {
    int idx = blockIdx.x * blockDim.x + threadIdx.x;
    const int n1 = S_ * VC_;
    if (idx < n1) {
        int s = idx / VC_, w = idx % VC_;
        g_acsT[idx] = acs[w * S_ + s];
    } else {
        int k = idx - n1;
        if (k >= VC_ * V_) return;
        int w = k / V_, v = k % V_;
        g_afcT[k] = afc[(size_t)v * VC_ + w];
    }
}

__global__ void cvt_to_h(const float* __restrict__ src, __half* __restrict__ dst, int n4) {
    int i = blockIdx.x * blockDim.x + threadIdx.x;
    if (i >= n4) return;
    float4 v = reinterpret_cast<const float4*>(src)[i];
    reinterpret_cast<uint2*>(dst)[i] = make_uint2(pack_h2(v.x, v.y), pack_h2(v.z, v.w));
}

// ---------------- channel mix: H fp32, Z2/Z3 fp16 ----------------
__global__ void chanmix(const float* __restrict__ Xin,
                        const float* __restrict__ W,
                        const float* __restrict__ b,
                        float* __restrict__ H,
                        __half* __restrict__ Z2,
                        __half* __restrict__ Z3) {
    __shared__ float4 sW[32 * 24];
    __shared__ float  sb[32];
    int r = blockIdx.x;
    const float* xr = Xin + (size_t)r * M_;
    for (int i = threadIdx.x; i < 32 * 24; i += 192)
        sW[i] = reinterpret_cast<const float4*>(W)[i];
    if (threadIdx.x < 32) sb[threadIdx.x] = b[threadIdx.x];
    __syncthreads();

    int nl = threadIdx.x;
    float xv[32];
    #pragma unroll
    for (int c = 0; c < 32; c++) xv[c] = xr[c * NL_ + nl];

    for (int o = 0; o < 32; o++) {
        const float4* wr = &sW[o * 24];
        float a0 = sb[o], a1 = 0.f, a2 = 0.f;
        #pragma unroll
        for (int c4 = 0; c4 < 8; c4++) {
            float4 w0 = wr[c4];
            float4 w1 = wr[8 + c4];
            float4 w2 = wr[16 + c4];
            float x0 = xv[c4 * 4], x1 = xv[c4 * 4 + 1], x2 = xv[c4 * 4 + 2], x3 = xv[c4 * 4 + 3];
            a0 = fmaf(w0.x, x0, fmaf(w0.y, x1, fmaf(w0.z, x2, fmaf(w0.w, x3, a0))));
            a1 = fmaf(w1.x, x0, fmaf(w1.y, x1, fmaf(w1.z, x2, fmaf(w1.w, x3, a1))));
            a2 = fmaf(w2.x, x0, fmaf(w2.y, x1, fmaf(w2.z, x2, fmaf(w2.w, x3, a2))));
        }
        size_t base = (size_t)r * M_ + o * NL_ + nl;
        H[base]  = a0;
        Z2[base] = __float2half_rn(a1);
        Z3[base] = __float2half_rn(a2);
    }
}

// ---------------- TN GEMM template: IS16 = operands already fp16 ----------------
#define STAGE_B 8192
template <int IS16>
__global__ void __launch_bounds__(256, 2)
gemm_core(const void* __restrict__ Av, const void* __restrict__ Bv, float* __restrict__ C,
          int Mo, int Mn, int kslice, int mode, float alpha,
          float* __restrict__ outp, int nodes, int obase) {
    __shared__ __align__(16) char smh[3 * STAGE_B];
    const uint32_t sbase = smem_u32(smh);

    const int zz = blockIdx.z;
    const size_t aoff = (size_t)zz * kslice * Mo;
    const size_t boff = (size_t)zz * kslice * Mn;
    C += (size_t)zz * Mo * Mn * (gridDim.z > 1 ? 1 : 0);

    const int bm = blockIdx.y * 128;
    const int bn = blockIdx.x * 128;
    const int tid  = threadIdx.x;
    const int lane = tid & 31;
    const int warp = tid >> 5;
    const int m_base = (warp >> 2) * 64;
    const int n_base = (warp & 3) * 32;

    const int lrow0 = warp;
    const int lc4   = (tid & 31) << 2;
    const int mg    = lc4 >> 3;
    const int hoff  = (lc4 & 7) * 2;

    const int gA  = lane >> 3;
    const int krA = (lane & 7) | ((gA & 2) << 2);
    int offA[4];
    #pragma unroll
    for (int i = 0; i < 4; i++) {
        int mgA = ((m_base + i * 16) >> 3) + (gA & 1);
        offA[i] = krA * 256 + ((mgA ^ (krA & 7)) << 4);
    }
    const int gB  = lane >> 3;
    const int krB = (lane & 7) | ((gB & 1) << 3);
    int offB[2];
    #pragma unroll
    for (int jp = 0; jp < 2; jp++) {
        int ngB = ((n_base + jp * 16) >> 3) + (gB >> 1);
        offB[jp] = krB * 256 + ((ngB ^ (krB & 7)) << 4);
    }

    float acc[4][4][4];
    #pragma unroll
    for (int i = 0; i < 4; i++)
        #pragma unroll
        for (int j = 0; j < 4; j++)
            #pragma unroll
            for (int t = 0; t < 4; t++) acc[i][j][t] = 0.f;

    const int nch = kslice >> 4;
    float4 va[2], vb[2];
    uint2  ha[2], hb[2];

    auto load_regs = [&](int ch) {
        if (ch >= nch) return;
        const int k0 = ch << 4;
        const bool aok = (bm + lc4 < Mo);
        #pragma unroll
        for (int h = 0; h < 2; h++) {
            const int kr = k0 + lrow0 + h * 8;
            if (IS16) {
                const __half* A16 = (const __half*)Av;
                const __half* B16 = (const __half*)Bv;
                ha[h] = aok ? *reinterpret_cast<const uint2*>(A16 + aoff + (size_t)kr * Mo + bm + lc4)
                            : make_uint2(0u, 0u);
                hb[h] = *reinterpret_cast<const uint2*>(B16 + boff + (size_t)kr * Mn + bn + lc4);
            } else {
                const float* A32 = (const float*)Av;
                const float* B32 = (const float*)Bv;
                va[h] = aok ? *reinterpret_cast<const float4*>(A32 + aoff + (size_t)kr * Mo + bm + lc4)
                            : make_float4(0.f, 0.f, 0.f, 0.f);
                vb[h] = *reinterpret_cast<const float4*>(B32 + boff + (size_t)kr * Mn + bn + lc4);
            }
        }
    };
    auto sts_regs = [&](int ch) {
        if (ch >= nch) return;
        char* stg = smh + (ch % 3) * STAGE_B;
        #pragma unroll
        for (int h = 0; h < 2; h++) {
            const int kr = lrow0 + h * 8;
            const int gsw = (mg ^ (kr & 7)) << 4;
            uint2 ua, ub;
            if (IS16) { ua = ha[h]; ub = hb[h]; }
            else {
                ua = make_uint2(pack_h2(va[h].x, va[h].y), pack_h2(va[h].z, va[h].w));
                ub = make_uint2(pack_h2(vb[h].x, vb[h].y), pack_h2(vb[h].z, vb[h].w));
            }
            *reinterpret_cast<uint2*>(stg + kr * 256 + gsw + hoff) = ua;
            *reinterpret_cast<uint2*>(stg + 4096 + kr * 256 + gsw + hoff) = ub;
        }
    };

    load_regs(0);
    sts_regs(0);
    load_regs(1);

    for (int ch = 0; ch < nch; ch++) {
        sts_regs(ch + 1);
        load_regs(ch + 2);
        __syncthreads();

        const uint32_t a_s = sbase + (uint32_t)((ch % 3) * STAGE_B);
        const uint32_t b_s = a_s + 4096u;

        unsigned af[4][4];
        #pragma unroll
        for (int i = 0; i < 4; i++)
            LDSM4T(af[i][0], af[i][1], af[i][2], af[i][3], a_s + offA[i]);
        unsigned bf[4][2];
        #pragma unroll
        for (int jp = 0; jp < 2; jp++) {
            unsigned r0, r1, r2, r3;
            LDSM4T(r0, r1, r2, r3, b_s + offB[jp]);
            bf[jp * 2][0] = r0;  bf[jp * 2][1] = r1;
            bf[jp * 2 + 1][0] = r2;  bf[jp * 2 + 1][1] = r3;
        }

        #pragma unroll
        for (int i = 0; i < 4; i++)
            #pragma unroll
            for (int j = 0; j < 4; j++) {
                asm volatile(
                    "mma.sync.aligned.m16n8k16.row.col.f32.f16.f16.f32 "
                    "{%0,%1,%2,%3},{%4,%5,%6,%7},{%8,%9},{%0,%1,%2,%3};\n"
                    : "+f"(acc[i][j][0]), "+f"(acc[i][j][1]),
                      "+f"(acc[i][j][2]), "+f"(acc[i][j][3])
                    : "r"(af[i][0]), "r"(af[i][1]), "r"(af[i][2]), "r"(af[i][3]),
                      "r"(bf[j][0]), "r"(bf[j][1]));
            }
    }

    const int gid = lane >> 2;
    const int qc  = lane & 3;

    int coff[4][2];
    if (outp) {
        #pragma unroll
        for (int j = 0; j < 4; j++) {
            int c0 = bn + n_base + j * 8 + qc * 2;
            coff[j][0] = out_coff(c0, nodes);
            coff[j][1] = out_coff(c0 + 1, nodes);
        }
    }

    #pragma unroll
    for (int i = 0; i < 4; i++) {
        int r0 = bm + m_base + i * 16 + gid;
        int r1 = r0 + 8;
        #pragma unroll
        for (int j = 0; j < 4; j++) {
            int col = bn + n_base + j * 8 + qc * 2;
            #pragma unroll
            for (int h = 0; h < 2; h++) {
                int row = h ? r1 : r0;
                if (row >= Mo) continue;
                float x0 = acc[i][j][h * 2 + 0];
                float x1 = acc[i][j][h * 2 + 1];
                float* cp = C + (size_t)row * Mn + col;
                float2 r;
                if (mode == 0) {
                    r = make_float2(x0, x1);
                } else {
                    float2 p = *reinterpret_cast<const float2*>(cp);
                    if (mode == 1) {
                        r = make_float2(p.x + x0, p.y + x1);
                    } else {
                        r = make_float2(p.x + alpha * fmaxf(x0, 0.f),
                                        p.y + alpha * fmaxf(x1, 0.f));
                    }
                }
                *reinterpret_cast<float2*>(cp) = r;
                if (outp) {
                    outp[obase + coff[j][0] + row * L_] = r.x;
                    outp[obase + coff[j][1] + row * L_] = r.y;
                }
            }
        }
    }
}

// ---------------- split-K reduce (optional permuted copy / transposed out) ----------
__global__ void reduceN(const float* __restrict__ p, float* __restrict__ C,
                        int n, int R, int mode, float alpha,
                        float* __restrict__ permOut,
                        float* __restrict__ outp, int nodes, int obase) {
    int idx = blockIdx.x * blockDim.x + threadIdx.x;
    if (idx >= n) return;
    float s = 0.f;
    for (int r = 0; r < R; r++) s += p[(size_t)r * n + idx];
    float v;
    if (mode == 0)      v = s;
    else if (mode == 1) v = C[idx] + s;
    else                v = C[idx] + alpha * fmaxf(s, 0.f);
    C[idx] = v;
    if (permOut) {
        // inverse perm: col m=(c,n,l) -> j = l*512 + n*32 + c
        int row = idx / M_, col = idx % M_;
        int c = col / NL_;
        int rem = col - c * NL_;
        int nn = rem / L_;
        int l = rem - nn * L_;
        permOut[(size_t)row * M_ + (l * 512 + nn * 32 + c)] = v;
    }
    if (outp) {
        int row = idx / M_, col = idx % M_;
        outp[obase + out_coff(col, nodes) + row * L_] = v;
    }
}

// ---------------- as_mat partials (grid S_ x 2, each half of j) ----------------
__global__ void asmat_kernel() {
    __shared__ float Ps[M_ / 2];
    int s = blockIdx.x, hf = blockIdx.y;
    int j0 = hf * (M_ / 2);
    for (int i = threadIdx.x; i < M_ / 2; i += blockDim.x)
        Ps[i] = g_Sxg[(size_t)s * M_ + j0 + i];
    __syncthreads();
    int warp = threadIdx.x >> 5, lane = threadIdx.x & 31;
    for (int t = warp; t < S_; t += 8) {
        float acc = 0.f;
        const float* qt = &g_SxgP[(size_t)t * M_ + j0];
        for (int j = lane; j < M_ / 2; j += 32)
            acc = fmaf(Ps[j], qt[j], acc);
        #pragma unroll
        for (int o = 16; o > 0; o >>= 1) acc += __shfl_down_sync(0xffffffffu, acc, o);
        if (lane == 0)
            g_asmatP[hf * S_ * S_ + s * S_ + t] = acc;
    }
}

// ---------------- sup0 / sup1 -> fp16 halves (combine asmat partials) ----------------
__global__ void supmat_kernel() {
    __shared__ float Ms[S_ * S_];
    int t = threadIdx.x;
    for (int i = t; i < S_ * S_; i += blockDim.x)
        Ms[i] = fmaxf(g_asmatP[i] + g_asmatP[S_ * S_ + i] - 0.5f, 0.f);
    __syncthreads();
    if (t >= S_) return;
    float vals[S_];
    {
        float rs = 0.f;
        for (int u = 0; u < S_; u++) rs += Ms[t * S_ + u];
        float dinv = rs > 0.f ? 1.f / rs : 0.f;
        float mx = -1e30f;
        for (int u = 0; u < S_; u++) { vals[u] = Ms[t * S_ + u] * dinv; mx = fmaxf(mx, vals[u]); }
        float se = 0.f;
        for (int u = 0; u < S_; u++) { vals[u] = expf(vals[u] - mx); se += vals[u]; }
        float inv = 1.f / se;
        for (int u = 0; u < S_; u++) g_sup01h[t * S_ + u] = __float2half_rn(vals[u] * inv);
    }
    {
        float cs = 0.f;
        for (int u = 0; u < S_; u++) cs += Ms[u * S_ + t];
        float dinv = cs > 0.f ? 1.f / cs : 0.f;
        float mx = -1e30f;
        for (int u = 0; u < S_; u++) { vals[u] = Ms[u * S_ + t] * dinv; mx = fmaxf(mx, vals[u]); }
        float se = 0.f;
        for (int u = 0; u < S_; u++) { vals[u] = expf(vals[u] - mx); se += vals[u]; }
        float inv = 1.f / se;
        for (int u = 0; u < S_; u++) g_sup01h[S_ * S_ + t * S_ + u] = __float2half_rn(vals[u] * inv);
    }
}

// ---------------- host side ----------------
static inline void launch_gemm(const void* A, const void* B, void* C,
                               int Mo, int K, int mode, float alpha, bool is16,
                               void* outp = nullptr, int nodes = 0, int obase = 0) {
    dim3 grid(M_ / 128, (Mo + 127) / 128, 1);
    if (is16)
        gemm_core<1><<<grid, 256>>>(A, B, (float*)C, Mo, M_, K, mode, alpha,
                                    (float*)outp, nodes, obase);
    else
        gemm_core<0><<<grid, 256>>>(A, B, (float*)C, Mo, M_, K, mode, alpha,
                                    (float*)outp, nodes, obase);
}
static inline void launch_gemm_sk(const void* A, const void* B, void* part, void* C,
                                  int Mo, int K, int R, int mode, float alpha, bool is16,
                                  void* permOut = nullptr,
                                  void* outp = nullptr, int nodes = 0, int obase = 0) {
    dim3 grid(M_ / 128, (Mo + 127) / 128, R);
    if (is16)
        gemm_core<1><<<grid, 256>>>(A, B, (float*)part, Mo, M_, K / R, 0, 0.f,
                                    nullptr, 0, 0);
    else
        gemm_core<0><<<grid, 256>>>(A, B, (float*)part, Mo, M_, K / R, 0, 0.f,
                                    nullptr, 0, 0);
    int n = Mo * M_;
    reduceN<<<(n + 255) / 256, 256>>>((const float*)part, (float*)C, n, R, mode, alpha,
                                      (float*)permOut, (float*)outp, nodes, obase);
}

extern "C" void kernel_launch(void* const* d_in, const int* in_sizes, int n_in,
                              void* d_out, int out_size) {
    (void)in_sizes; (void)n_in; (void)out_size;
    const float* x         = (const float*)d_in[0];
    const float* support   = (const float*)d_in[1];
    const float* support_c = (const float*)d_in[2];
    const float* acs       = (const float*)d_in[3];
    const float* afc       = (const float*)d_in[4];
    const float* W         = (const float*)d_in[5];
    const float* b         = (const float*)d_in[6];
    float* out = (float*)d_out;

    void *pX, *pZ23h, *pHF, *pXc, *pZc23h, *pHC;
    void *pSxg, *pSxgP, *pZs23h, *pHS, *psup01h, *pacsT, *pafcT, *ppart, *psup16, *psupc16;
    cudaGetSymbolAddress(&pX, g_X);         cudaGetSymbolAddress(&pZ23h, g_Z23h);
    cudaGetSymbolAddress(&pHF, g_HF);       cudaGetSymbolAddress(&pXc, g_Xc);
    cudaGetSymbolAddress(&pZc23h, g_Zc23h); cudaGetSymbolAddress(&pHC, g_HC);
    cudaGetSymbolAddress(&pSxg, g_Sxg);     cudaGetSymbolAddress(&pSxgP, g_SxgP);
    cudaGetSymbolAddress(&pZs23h, g_Zs23h); cudaGetSymbolAddress(&pHS, g_HS);
    cudaGetSymbolAddress(&psup01h, g_sup01h);
    cudaGetSymbolAddress(&pacsT, g_acsT);   cudaGetSymbolAddress(&pafcT, g_afcT);
    cudaGetSymbolAddress(&ppart, g_part);   cudaGetSymbolAddress(&psup16, g_sup16);
    cudaGetSymbolAddress(&psupc16, g_supc16);

    __half* Z2  = (__half*)pZ23h;
    __half* Z3  = Z2 + (size_t)V_ * M_;
    __half* Zc2 = (__half*)pZc23h;
    __half* Zc3 = Zc2 + (size_t)VC_ * M_;
    __half* Zs2 = (__half*)pZs23h;
    __half* Zs3 = Zs2 + (size_t)S_ * M_;

    // 1. layout prep
    transpose_in<<<(N_ * C_ * V_ * L_ + 255) / 256, 256>>>(x);
    prep_t<<<(S_ * VC_ + VC_ * V_ + 255) / 256, 256>>>(acs, afc);
    cvt_to_h<<<(2 * V_ * V_ / 4 + 255) / 256, 256>>>(support, (__half*)psup16, 2 * V_ * V_ / 4);
    cvt_to_h<<<(2 * VC_ * VC_ / 4 + 255) / 256, 256>>>(support_c, (__half*)psupc16, 2 * VC_ * VC_ / 4);

    // 2. fine level: HF = b + W1 x; merged GEMM (fp16 operands)
    chanmix<<<V_, 192>>>((const float*)pX, W, b, (float*)pHF, Z2, Z3);
    launch_gemm(psup16, pZ23h, pHF, V_, 2 * V_, 1, 1.f, true);

    // 3. coarse level
    launch_gemm_sk(afc, pX, ppart, pXc, VC_, V_, 2, 0, 0.f, false);
    chanmix<<<VC_, 192>>>((const float*)pXc, W, b, (float*)pHC, Zc2, Zc3);
    launch_gemm_sk(psupc16, pZc23h, ppart, pHC, VC_, 2 * VC_, 2, 1, 0.f, true);

    // 4. super level input; reduce also emits the permuted copy (no extra pass)
    launch_gemm_sk(acs, pXc, ppart, pSxg, S_, VC_, 4, 0, 0.f, false, pSxgP);

    // 5. data-dependent super supports (exact fp32)
    asmat_kernel<<<dim3(S_, 2), 256>>>();
    supmat_kernel<<<1, 64>>>();

    // 6. super gcn
    chanmix<<<S_, 192>>>((const float*)pSxg, W, b, (float*)pHS, Zs2, Zs3);
    launch_gemm_sk(psup01h, pZs23h, ppart, pHS, S_, 2 * S_, 2, 1, 0.f, true);

    // 7. fusions; final writers emit transposed outputs
    launch_gemm_sk(pacsT, pHS, ppart, pHC, VC_, S_, 2, 2, N1F, false);
    launch_gemm(pafcT, pHC, pHF, V_, VC_, 2, N2F, false, out, V_, 0);
    launch_gemm_sk(afc, pHF, ppart, pHC, VC_, V_, 2, 2, N3F, false, nullptr, out, VC_, HFSZ);
    launch_gemm_sk(acs, pHC, ppart, pHS, S_, VC_, 4, 2, N4F, false, nullptr, out, S_, HFSZ + HCSZ);
}